// round 8
// baseline (speedup 1.0000x reference)
#include <cuda_runtime.h>
#include <cstdint>

#define B_  8
#define C_  32
#define H_  64
#define W_  64
#define F_  64
#define TH  16               // output rows per CTA (4 per warp)
#define NT  128
#define RW  6                // staged rows per warp (4 + halo)
#define CW  66               // staged cols (64 + halo)
#define WSTR (RW * CW)       // 396 floats per warp buffer
#define HW  (H_ * W_)
#define DBUF (4 * WSTR * 4)  // byte distance between ping/pong buffers

typedef unsigned long long ull;

// ---- packed f32x2 helpers (sm_10x packed fp32 pipe, PTX-only) ----
__device__ __forceinline__ ull pk2(float lo, float hi) {
    ull r; asm("mov.b64 %0, {%1, %2};" : "=l"(r) : "f"(lo), "f"(hi)); return r;
}
__device__ __forceinline__ void upk2(ull v, float& lo, float& hi) {
    asm("mov.b64 {%0, %1}, %2;" : "=f"(lo), "=f"(hi) : "l"(v));
}
__device__ __forceinline__ ull ffma2(ull a, ull b, ull c) {
    ull d; asm("fma.rn.f32x2 %0, %1, %2, %3;" : "=l"(d) : "l"(a), "l"(b), "l"(c)); return d;
}
__device__ __forceinline__ ull fmul2(ull a, ull b) {
    ull d; asm("mul.rn.f32x2 %0, %1, %2;" : "=l"(d) : "l"(a), "l"(b)); return d;
}
__device__ __forceinline__ ull fadd2(ull a, ull b) {
    ull d; asm("add.rn.f32x2 %0, %1, %2;" : "=l"(d) : "l"(a), "l"(b)); return d;
}
__device__ __forceinline__ ull and64(ull a, ull b) {
    ull d; asm("and.b64 %0, %1, %2;" : "=l"(d) : "l"(a), "l"(b)); return d;
}
__device__ __forceinline__ float frcp(float x) {
    float r; asm("rcp.approx.ftz.f32 %0, %1;" : "=f"(r) : "f"(x)); return r;
}
__device__ __forceinline__ uint32_t s2u32(const void* p) {
    uint32_t a;
    asm("{ .reg .u64 t; cvta.to.shared.u64 t, %1; cvt.u32.u64 %0, t; }"
        : "=r"(a) : "l"(p));
    return a;
}
// cp.async 4B with zfill via src-size (0 => zero-fill destination, no read)
__device__ __forceinline__ void cpa4(uint32_t dst, const float* src, int ssz) {
    asm volatile("cp.async.ca.shared.global [%0], [%1], 4, %2;"
                 :: "r"(dst), "l"(src), "r"(ssz) : "memory");
}
__device__ __forceinline__ void cpa_commit() {
    asm volatile("cp.async.commit_group;" ::: "memory");
}
template <int N>
__device__ __forceinline__ void cpa_wait() {
    asm volatile("cp.async.wait_group %0;" :: "n"(N) : "memory");
}

__global__ __launch_bounds__(NT, 6)
void kan_kernel(const float* __restrict__ x,
                const float* __restrict__ numc,
                const float* __restrict__ denc,
                float* __restrict__ out)
{
    // coef_s[(tap*32 + c)*10 + j]: j=0..5 num a0..a5, j=6..9 den b1..b4,
    // duplicated into both f32x2 lanes; entry = 80B so 16B-aligned for LDS.128.
    __shared__ __align__(16) ull   coef_s[9 * C_ * 10];   // 23040 B
    __shared__ __align__(16) float xs[2][4][WSTR];        // 12672 B (per-warp ping/pong)

    const int tile = blockIdx.x;          // 0..3
    const int f    = blockIdx.y;
    const int b    = blockIdx.z;
    const int h0   = tile * TH;
    const int tid  = threadIdx.x;
    const int wid  = tid >> 5, lane = tid & 31;

    const float* xb_gl = x + ((size_t)b * C_) * HW;

    // ---- channel-invariant staging precompute (warp rows 4wid-1 .. 4wid+4) ----
    int rowoff[RW];      // source row byte-offset (clamped when invalid)
    int g4[RW];          // 4 if row in range else 0 (cp.async src-size)
    #pragma unroll
    for (int r = 0; r < RW; ++r) {
        int gh = h0 + 4 * wid - 1 + r;
        bool v = (unsigned)gh < (unsigned)H_;
        rowoff[r] = (v ? gh : 0) * W_;
        g4[r] = v ? 4 : 0;
    }
    const int off0 = (lane == 0) ? 0 : (lane - 1);  // slot0 src col (clamped)
    const uint32_t d0 = s2u32(&xs[0][wid][0]) + lane * 4u;

    // per-warp stage of one channel tile into dst buffer (no CTA barrier!)
    auto stage = [&](const float* xc, uint32_t dst) {
        #pragma unroll
        for (int r = 0; r < RW; ++r) {
            const float* rp = xc + rowoff[r];
            uint32_t dr = dst + (uint32_t)(r * (CW * 4));
            int s0 = lane ? g4[r] : 0;                 // col lane -> gw = lane-1
            cpa4(dr,            rp + off0,      s0);
            cpa4(dr + 32 * 4,   rp + lane + 31, g4[r]); // col lane+32
            if (lane < 2)                               // cols 64,65 -> gw 63, 64(inv)
                cpa4(dr + 64 * 4, rp + 63, (lane == 0) ? g4[r] : 0);
        }
    };

    // ---- prefetch channel 0 (per-warp) ----
    stage(xb_gl, d0);
    cpa_commit();

    // ---- stage filter-f coefficients (duplicated f32x2), CTA-cooperative ----
    {
        const float* np = numc + (size_t)f * 9 * C_ * 6;
        for (int i = tid; i < 9 * C_ * 6; i += NT) {
            int t = i / (C_ * 6);
            int r = i - t * (C_ * 6);
            int c = r / 6, j = r - c * 6;
            float v = np[i];
            coef_s[(t * C_ + c) * 10 + j] = pk2(v, v);
        }
        const float* dp = denc + (size_t)f * 9 * C_ * 4;
        for (int i = tid; i < 9 * C_ * 4; i += NT) {
            int t = i / (C_ * 4);
            int r = i - t * (C_ * 4);
            int c = r / 4, j = r - c * 4;
            float v = dp[i];
            coef_s[(t * C_ + c) * 10 + 6 + j] = pk2(v, v);
        }
    }
    __syncthreads();   // the ONLY CTA barrier: coef_s visible to all

    const ull ABS2 = 0x7FFFFFFF7FFFFFFFULL;
    const ull ONE2 = pk2(1.0f, 1.0f);

    ull acc[4];
    #pragma unroll
    for (int m = 0; m < 4; ++m) acc[m] = 0;

    const float* nxt = xb_gl + HW;        // channel 1 source base

    #pragma unroll 1
    for (int c = 0; c < C_; ++c) {
        if (c + 1 < C_) {
            stage(nxt, d0 + (uint32_t)(((c + 1) & 1) * DBUF));
            nxt += HW;
            cpa_commit();
            cpa_wait<1>();               // channel c's buffer complete (this warp)
        } else {
            cpa_wait<0>();
        }
        __syncwarp();                     // cross-lane visibility within warp

        const float* wcol = &xs[c & 1][wid][0] + 2 * lane;

        #pragma unroll
        for (int ta = 0; ta < 3; ++ta) {
            // rows m+ta (local), cols 2lane..2lane+3 as two float2 each
            float2 A[4], Bv[4];
            #pragma unroll
            for (int m = 0; m < 4; ++m) {
                const float* rp = wcol + (ta + m) * CW;
                A[m]  = *(const float2*)rp;
                Bv[m] = *(const float2*)(rp + 2);
            }
            #pragma unroll
            for (int tb = 0; tb < 3; ++tb) {
                const ulonglong2* cs2 = reinterpret_cast<const ulonglong2*>(
                    &coef_s[((ta * 3 + tb) * C_ + c) * 10]);
                const ulonglong2 v0 = cs2[0], v1 = cs2[1], v2 = cs2[2],
                                 v3 = cs2[3], v4 = cs2[4];
                const ull a0 = v0.x, a1 = v0.y, a2 = v1.x, a3 = v1.y,
                          a4 = v2.x, a5 = v2.y;
                const ull b1 = v3.x, b2 = v3.y, b3 = v4.x, b4 = v4.y;

                #pragma unroll
                for (int m = 0; m < 4; ++m) {
                    ull xp = (tb == 0) ? pk2(A[m].x, A[m].y)
                           : (tb == 1) ? pk2(A[m].y, Bv[m].x)
                                       : pk2(Bv[m].x, Bv[m].y);

                    ull num = ffma2(a5, xp, a4);
                    num = ffma2(num, xp, a3);
                    num = ffma2(num, xp, a2);
                    num = ffma2(num, xp, a1);
                    num = ffma2(num, xp, a0);
                    ull q = ffma2(b4, xp, b3);
                    q = ffma2(q, xp, b2);
                    q = ffma2(q, xp, b1);
                    ull t = and64(fmul2(q, xp), ABS2);
                    ull den = fadd2(ONE2, t);

                    float dlo, dhi; upk2(den, dlo, dhi);
                    ull inv = pk2(frcp(dlo), frcp(dhi));
                    acc[m] = ffma2(num, inv, acc[m]);
                }
            }
        }
        __syncwarp();   // all lanes done reading buf before next overwrite
    }

    // ---- write out[b][f][h0+4wid+m][2lane .. 2lane+1] ----
    float* ob = out + (((size_t)b * F_ + f) * H_ + h0 + 4 * wid) * W_ + 2 * lane;
    #pragma unroll
    for (int m = 0; m < 4; ++m) {
        float lo, hi; upk2(acc[m], lo, hi);
        *(float2*)(ob + m * W_) = make_float2(lo, hi);
    }
}

extern "C" void kernel_launch(void* const* d_in, const int* in_sizes, int n_in,
                              void* d_out, int out_size)
{
    const float* x  = (const float*)d_in[0];
    const float* nc = (const float*)d_in[1];
    const float* dc = (const float*)d_in[2];
    float* out = (float*)d_out;

    dim3 grid(H_ / TH, F_, B_);   // 4 x 64 x 8 = 2048 CTAs
    kan_kernel<<<grid, NT>>>(x, nc, dc, out);
}

// round 11
// speedup vs baseline: 1.0987x; 1.0987x over previous
#include <cuda_runtime.h>
#include <cstdint>

#define B_  8
#define C_  32
#define H_  64
#define W_  64
#define F_  64
#define TH  16               // output rows per CTA (4 per warp)
#define NT  128
#define RW  6                // staged rows per warp (4 + halo)
#define CW  66               // staged cols (64 + halo); 264B row, 8B-aligned
#define WSTR (RW * CW)       // 396 floats per warp buffer
#define HW  (H_ * W_)
#define DBUF (4 * WSTR * 4)  // byte distance between ping/pong buffers

typedef unsigned long long ull;

// ---- packed f32x2 helpers (sm_10x packed fp32 pipe, PTX-only) ----
__device__ __forceinline__ ull pk2(float lo, float hi) {
    ull r; asm("mov.b64 %0, {%1, %2};" : "=l"(r) : "f"(lo), "f"(hi)); return r;
}
__device__ __forceinline__ void upk2(ull v, float& lo, float& hi) {
    asm("mov.b64 {%0, %1}, %2;" : "=f"(lo), "=f"(hi) : "l"(v));
}
__device__ __forceinline__ ull ffma2(ull a, ull b, ull c) {
    ull d; asm("fma.rn.f32x2 %0, %1, %2, %3;" : "=l"(d) : "l"(a), "l"(b), "l"(c)); return d;
}
__device__ __forceinline__ ull fmul2(ull a, ull b) {
    ull d; asm("mul.rn.f32x2 %0, %1, %2;" : "=l"(d) : "l"(a), "l"(b)); return d;
}
__device__ __forceinline__ ull fadd2(ull a, ull b) {
    ull d; asm("add.rn.f32x2 %0, %1, %2;" : "=l"(d) : "l"(a), "l"(b)); return d;
}
__device__ __forceinline__ ull and64(ull a, ull b) {
    ull d; asm("and.b64 %0, %1, %2;" : "=l"(d) : "l"(a), "l"(b)); return d;
}
// packed reciprocal: inv = {rcp(d.lo), rcp(d.hi)} — internal regs so ptxas
// coalesces the surrounding movs (MUFU dests land in an aligned pair).
__device__ __forceinline__ ull rcp2(ull den) {
    ull r;
    asm("{\n\t.reg .f32 d0,d1,r0,r1;\n\t"
        "mov.b64 {d0,d1}, %1;\n\t"
        "rcp.approx.ftz.f32 r0, d0;\n\t"
        "rcp.approx.ftz.f32 r1, d1;\n\t"
        "mov.b64 %0, {r0,r1};\n\t}"
        : "=l"(r) : "l"(den));
    return r;
}
// mid pair {a.hi, b.lo} for tb=1
__device__ __forceinline__ ull pkhl(ull a, ull b) {
    ull r;
    asm("{\n\t.reg .f32 al,ah,bl,bh;\n\t"
        "mov.b64 {al,ah}, %1;\n\t"
        "mov.b64 {bl,bh}, %2;\n\t"
        "mov.b64 %0, {ah,bl};\n\t}"
        : "=l"(r) : "l"(a), "l"(b));
    return r;
}
__device__ __forceinline__ uint32_t s2u32(const void* p) {
    uint32_t a;
    asm("{ .reg .u64 t; cvta.to.shared.u64 t, %1; cvt.u32.u64 %0, t; }"
        : "=r"(a) : "l"(p));
    return a;
}
// cp.async 4B with zfill via src-size (0 => zero-fill destination, no read)
__device__ __forceinline__ void cpa4(uint32_t dst, const float* src, int ssz) {
    asm volatile("cp.async.ca.shared.global [%0], [%1], 4, %2;"
                 :: "r"(dst), "l"(src), "r"(ssz) : "memory");
}
__device__ __forceinline__ void cpa_commit() {
    asm volatile("cp.async.commit_group;" ::: "memory");
}
template <int N>
__device__ __forceinline__ void cpa_wait() {
    asm volatile("cp.async.wait_group %0;" :: "n"(N) : "memory");
}

__global__ __launch_bounds__(NT, 6)
void kan_kernel(const float* __restrict__ x,
                const float* __restrict__ numc,
                const float* __restrict__ denc,
                float* __restrict__ out)
{
    // coef_s[(tap*32 + c)*10 + j]: j=0..5 num a0..a5, j=6..9 den b1..b4,
    // duplicated into both f32x2 lanes; entry = 80B => 16B-aligned LDS.128.
    __shared__ __align__(16) ull   coef_s[9 * C_ * 10];   // 23040 B
    __shared__ __align__(16) float xs[2][4][WSTR];        // 12672 B (per-warp ping/pong)

    const int tile = blockIdx.x;          // 0..3
    const int f    = blockIdx.y;
    const int b    = blockIdx.z;
    const int h0   = tile * TH;
    const int tid  = threadIdx.x;
    const int wid  = tid >> 5, lane = tid & 31;

    const float* xb_gl = x + ((size_t)b * C_) * HW;

    const int hbase = h0 + 4 * wid - 1;             // first staged row
    const int off0  = (lane == 0) ? 0 : (lane - 1); // slot0 src col (clamped)
    const uint32_t d0 = s2u32(&xs[0][wid][0]) + lane * 4u;

    // per-warp stage of one channel tile (bounds recomputed -> fewer live regs)
    auto stage = [&](const float* xc, uint32_t dst) {
        #pragma unroll
        for (int r = 0; r < RW; ++r) {
            int gh = hbase + r;
            bool v = (unsigned)gh < (unsigned)H_;
            const float* rp = xc + (v ? gh : 0) * W_;
            int g4 = v ? 4 : 0;
            uint32_t dr = dst + (uint32_t)(r * (CW * 4));
            cpa4(dr,          rp + off0,      lane ? g4 : 0);   // col lane (gw=lane-1)
            cpa4(dr + 32 * 4, rp + lane + 31, g4);              // col lane+32
            if (lane < 2)                                       // cols 64,65
                cpa4(dr + 64 * 4, rp + 63, (lane == 0) ? g4 : 0);
        }
    };

    // ---- prefetch channel 0 (per-warp) ----
    stage(xb_gl, d0);
    cpa_commit();

    // ---- stage filter-f coefficients (duplicated f32x2), CTA-cooperative ----
    {
        const float* np = numc + (size_t)f * 9 * C_ * 6;
        for (int i = tid; i < 9 * C_ * 6; i += NT) {
            int t = i / (C_ * 6);
            int r = i - t * (C_ * 6);
            int c = r / 6, j = r - c * 6;
            float v = np[i];
            coef_s[(t * C_ + c) * 10 + j] = pk2(v, v);
        }
        const float* dp = denc + (size_t)f * 9 * C_ * 4;
        for (int i = tid; i < 9 * C_ * 4; i += NT) {
            int t = i / (C_ * 4);
            int r = i - t * (C_ * 4);
            int c = r / 4, j = r - c * 4;
            float v = dp[i];
            coef_s[(t * C_ + c) * 10 + 6 + j] = pk2(v, v);
        }
    }
    __syncthreads();   // the ONLY CTA barrier: coef_s visible to all

    const ull ABS2 = 0x7FFFFFFF7FFFFFFFULL;
    const ull ONE2 = pk2(1.0f, 1.0f);

    ull acc[4];
    #pragma unroll
    for (int m = 0; m < 4; ++m) acc[m] = 0;

    const float* nxt = xb_gl + HW;        // channel 1 source base

    #pragma unroll 1
    for (int c = 0; c < C_; ++c) {
        if (c + 1 < C_) {
            stage(nxt, d0 + (uint32_t)(((c + 1) & 1) * DBUF));
            nxt += HW;
            cpa_commit();
            cpa_wait<1>();               // channel c's buffer complete (this warp)
        } else {
            cpa_wait<0>();
        }
        __syncwarp();                     // cross-lane visibility within warp

        // x pairs loaded directly as packed ull (8B-aligned: 2*lane floats in)
        const char* wbase = (const char*)&xs[c & 1][wid][0] + lane * 8;

        #pragma unroll
        for (int ta = 0; ta < 3; ++ta) {
            ull A64[4], B64[4];
            #pragma unroll
            for (int m = 0; m < 4; ++m) {
                const ull* rp = (const ull*)(wbase + (ta + m) * (CW * 4));
                A64[m] = rp[0];           // cols 2l, 2l+1
                B64[m] = rp[1];           // cols 2l+2, 2l+3
            }
            #pragma unroll
            for (int tb = 0; tb < 3; ++tb) {
                ull xp[4];
                #pragma unroll
                for (int m = 0; m < 4; ++m)
                    xp[m] = (tb == 0) ? A64[m]
                          : (tb == 2) ? B64[m]
                                      : pkhl(A64[m], B64[m]);

                const ulonglong2* cs2 = reinterpret_cast<const ulonglong2*>(
                    &coef_s[((ta * 3 + tb) * C_ + c) * 10]);

                // step-synchronous Horner across the 4 pairs:
                // one coef ulonglong2 live at a time => 4-way chain ILP fits regs.
                ull num[4], q[4];
                {
                    const ulonglong2 v2 = cs2[2];          // (a4, a5)
                    #pragma unroll
                    for (int m = 0; m < 4; ++m) num[m] = ffma2(v2.y, xp[m], v2.x);
                }
                {
                    const ulonglong2 v4 = cs2[4];          // (b3, b4)
                    #pragma unroll
                    for (int m = 0; m < 4; ++m) q[m] = ffma2(v4.y, xp[m], v4.x);
                }
                {
                    const ulonglong2 v1 = cs2[1];          // (a2, a3)
                    #pragma unroll
                    for (int m = 0; m < 4; ++m) num[m] = ffma2(num[m], xp[m], v1.y);
                    #pragma unroll
                    for (int m = 0; m < 4; ++m) num[m] = ffma2(num[m], xp[m], v1.x);
                }
                {
                    const ulonglong2 v3 = cs2[3];          // (b1, b2)
                    #pragma unroll
                    for (int m = 0; m < 4; ++m) q[m] = ffma2(q[m], xp[m], v3.y);
                    #pragma unroll
                    for (int m = 0; m < 4; ++m) q[m] = ffma2(q[m], xp[m], v3.x);
                }
                {
                    const ulonglong2 v0 = cs2[0];          // (a0, a1)
                    #pragma unroll
                    for (int m = 0; m < 4; ++m) num[m] = ffma2(num[m], xp[m], v0.y);
                    #pragma unroll
                    for (int m = 0; m < 4; ++m) num[m] = ffma2(num[m], xp[m], v0.x);
                }
                #pragma unroll
                for (int m = 0; m < 4; ++m) {
                    ull t   = fmul2(q[m], xp[m]);
                    ull den = fadd2(ONE2, and64(t, ABS2));
                    ull inv = rcp2(den);
                    acc[m]  = ffma2(num[m], inv, acc[m]);
                }
            }
        }
        __syncwarp();   // all lanes done reading buf before next overwrite
    }

    // ---- write out[b][f][h0+4wid+m][2lane .. 2lane+1] ----
    float* ob = out + (((size_t)b * F_ + f) * H_ + h0 + 4 * wid) * W_ + 2 * lane;
    #pragma unroll
    for (int m = 0; m < 4; ++m) {
        float lo, hi; upk2(acc[m], lo, hi);
        *(float2*)(ob + m * W_) = make_float2(lo, hi);
    }
}

extern "C" void kernel_launch(void* const* d_in, const int* in_sizes, int n_in,
                              void* d_out, int out_size)
{
    const float* x  = (const float*)d_in[0];
    const float* nc = (const float*)d_in[1];
    const float* dc = (const float*)d_in[2];
    float* out = (float*)d_out;

    dim3 grid(H_ / TH, F_, B_);   // 4 x 64 x 8 = 2048 CTAs
    kan_kernel<<<grid, NT>>>(x, nc, dc, out);
}